// round 1
// baseline (speedup 1.0000x reference)
#include <cuda_runtime.h>
#include <cuda_fp16.h>
#include <mma.h>
using namespace nvcuda;

#define Bb 16
#define Nn 2048
#define Hh 128

// ---------------- scratch (device globals; no allocation allowed) ----------------
__device__ __half g_Ah[(size_t)Bb * Nn * Nn];      // adj -> fp16 with self loops, [b][j][i]
__device__ float  g_deg[Bb * Nn];
__device__ float  g_dis[Bb * Nn];
__device__ __half g_Xs[(size_t)Bb * Hh * Nn];      // XsT buffers (H x N per batch)
__device__ __half g_h [(size_t)Bb * Hh * Nn];
__device__ __half g_a1[(size_t)Bb * Hh * Nn];
__device__ __half g_a2[(size_t)Bb * Hh * Nn];
__device__ __half g_w16[4 * Hh * Hh];              // fp16 copies: W2, W3, A1_low, A2
__device__ float  g_pool[Bb * Hh];
__device__ float  g_bias1[Bb * Hh];
__device__ float  g_scores[Bb * Nn];

// ---------------- degree + fp16 conversion (fused single pass over adj) ----------------
__global__ void k_deg_convert(const int* __restrict__ adj) {
    int b  = blockIdx.y;
    int j0 = blockIdx.x * 64;
    int tid = threadIdx.x;
    float sum[8];
#pragma unroll
    for (int s = 0; s < 8; s++) sum[s] = 0.f;
    const int*  base  = adj  + ((size_t)b * Nn + j0) * Nn;
    __half*     obase = g_Ah + ((size_t)b * Nn + j0) * Nn;
    for (int r = 0; r < 64; r++) {
        int j = j0 + r;
        const int* row = base + (size_t)r * Nn;
        __half* orow = obase + (size_t)r * Nn;
#pragma unroll
        for (int s = 0; s < 8; s++) {
            int c = tid + s * 256;
            int v = row[c];
            float a = (v != 0 || j == c) ? 1.f : 0.f;   // add_remaining_self_loops
            orow[c] = __float2half(a);
            sum[s] += a;
        }
    }
#pragma unroll
    for (int s = 0; s < 8; s++) atomicAdd(&g_deg[b * Nn + tid + s * 256], sum[s]);
}

__global__ void k_dis() {
    int i = blockIdx.x * 256 + threadIdx.x;
    g_dis[i] = rsqrtf(g_deg[i]);
}

// convert the four 128x128 fp32 weight blocks to fp16 (A1_low = first 128 rows of A1)
__global__ void k_convw(const float* __restrict__ W2, const float* __restrict__ W3,
                        const float* __restrict__ A1, const float* __restrict__ A2) {
    int i = blockIdx.x * 256 + threadIdx.x;          // 16384 each
    g_w16[i]                 = __float2half(W2[i]);
    g_w16[Hh * Hh + i]       = __float2half(W3[i]);
    g_w16[2 * Hh * Hh + i]   = __float2half(A1[i]);  // rows 0..127 of (384,128) row-major
    g_w16[3 * Hh * Hh + i]   = __float2half(A2[i]);
}

// Layer-1 prologue: XsT[b][h][j] = dis[j] * (f[j,0]*W1[0,h] + f[j,1]*W1[1,h])
__global__ void k_xs1(const float* __restrict__ f, const float* __restrict__ W1) {
    int b = blockIdx.z, h = blockIdx.y;
    int j = blockIdx.x * 256 + threadIdx.x;
    float w0 = W1[h], w1 = W1[Hh + h];
    float f0 = f[((size_t)b * Nn + j) * 2];
    float f1 = f[((size_t)b * Nn + j) * 2 + 1];
    g_Xs[((size_t)b * Hh + h) * Nn + j] = __float2half(g_dis[b * Nn + j] * (f0 * w0 + f1 * w1));
}

// ---------------- WMMA GEMM: D(128 x Ntile) = A(128 x K) * B(K x Ntile), fused epilogue ----
#define BM 128
#define BN 64
#define BK 64
#define LDA_S 80
#define LDB_S 80
#define LDC_S 80

__global__ void k_gemm(const __half* __restrict__ gA, int lda, int aCol, size_t sA,
                       const __half* __restrict__ gB, size_t sB,
                       __half* __restrict__ gC, size_t sC, int K,
                       const float* __restrict__ cscale,   // per (b, n) column scale (dis) or null
                       const float* __restrict__ rbias,    // [128] row bias or null
                       const float* __restrict__ brbias,   // [b*128 + m] per-batch row bias or null
                       int doRelu)
{
    extern __shared__ char smem[];
    __half* As = (__half*)smem;                     // BM x LDA_S
    __half* Bs = (__half*)(smem + BM * LDA_S * 2);  // BK x LDB_S
    int b  = blockIdx.y;
    int n0 = blockIdx.x * BN;
    const __half* A  = gA + (size_t)b * sA;
    const __half* Bp = gB + (size_t)b * sB;
    int tid  = threadIdx.x;
    int warp = tid >> 5;
    int wm = warp >> 1, wn = warp & 1;

    wmma::fragment<wmma::accumulator, 16, 16, 16, float> acc[4][2];
#pragma unroll
    for (int i = 0; i < 4; i++)
#pragma unroll
        for (int j = 0; j < 2; j++) wmma::fill_fragment(acc[i][j], 0.f);

    for (int k0 = 0; k0 < K; k0 += BK) {
        if (aCol) {                                  // weights: col-major (m fast) load
            for (int idx = tid; idx < BM * BK; idx += 128) {
                int m = idx & (BM - 1), k = idx >> 7;
                As[m * LDA_S + k] = A[(size_t)(k0 + k) * lda + m];
            }
        } else {                                     // row-major, vectorized 8 halves
#pragma unroll
            for (int t = 0; t < 8; t++) {
                int idx = tid + t * 128;
                int m = idx >> 3, kg = (idx & 7) << 3;
                *(uint4*)(As + m * LDA_S + kg) =
                    *(const uint4*)(A + (size_t)m * lda + k0 + kg);
            }
        }
#pragma unroll
        for (int t = 0; t < 4; t++) {
            int idx = tid + t * 128;
            int k = idx >> 3, ng = (idx & 7) << 3;
            *(uint4*)(Bs + k * LDB_S + ng) =
                *(const uint4*)(Bp + (size_t)(k0 + k) * Nn + n0 + ng);
        }
        __syncthreads();
#pragma unroll
        for (int kk = 0; kk < BK; kk += 16) {
            wmma::fragment<wmma::matrix_a, 16, 16, 16, __half, wmma::row_major> af[4];
            wmma::fragment<wmma::matrix_b, 16, 16, 16, __half, wmma::row_major> bf[2];
#pragma unroll
            for (int i = 0; i < 4; i++)
                wmma::load_matrix_sync(af[i], As + (wm * 64 + i * 16) * LDA_S + kk, LDA_S);
#pragma unroll
            for (int j = 0; j < 2; j++)
                wmma::load_matrix_sync(bf[j], Bs + kk * LDB_S + wn * 32 + j * 16, LDB_S);
#pragma unroll
            for (int i = 0; i < 4; i++)
#pragma unroll
                for (int j = 0; j < 2; j++)
                    wmma::mma_sync(acc[i][j], af[i], bf[j], acc[i][j]);
        }
        __syncthreads();
    }
    float* Cs = (float*)smem;                        // BM x LDC_S (reuses operand smem)
#pragma unroll
    for (int i = 0; i < 4; i++)
#pragma unroll
        for (int j = 0; j < 2; j++)
            wmma::store_matrix_sync(Cs + (wm * 64 + i * 16) * LDC_S + wn * 32 + j * 16,
                                    acc[i][j], LDC_S, wmma::mem_row_major);
    __syncthreads();
    const float* cs = cscale ? cscale + b * Nn + n0 : nullptr;
    const float* bbp = brbias ? brbias + b * Hh : nullptr;
    for (int idx = tid; idx < BM * BN; idx += 128) {
        int m = idx >> 6, n = idx & 63;
        float v = Cs[m * LDC_S + n];
        if (cs)    v *= cs[n];
        if (rbias) v += rbias[m];
        if (bbp)   v += bbp[m];
        if (doRelu) v = fmaxf(v, 0.f);
        gC[(size_t)b * sC + (size_t)m * Nn + n0 + n] = __float2half(v);
    }
}

// ---------------- pool, actor bias, scores, finals ----------------
__global__ void k_pool() {
    int b = blockIdx.y;
    int warp = threadIdx.x / 32, lane = threadIdx.x % 32;
    int h = blockIdx.x * 8 + warp;
    const __half* row = g_h + ((size_t)b * Hh + h) * Nn;
    float s = 0.f;
    for (int i = lane; i < Nn; i += 32) s += __half2float(row[i]);
#pragma unroll
    for (int o = 16; o > 0; o >>= 1) s += __shfl_down_sync(0xffffffff, s, o);
    if (lane == 0) g_pool[b * Hh + h] = s / (float)Nn;
}

__global__ void k_bias1(const float* __restrict__ A1, const float* __restrict__ ab1,
                        const float* __restrict__ ms) {
    int b = blockIdx.x, h = threadIdx.x;
    float acc = ab1[h];
    for (int k = 0; k < Hh; k++)
        acc += g_pool[b * Hh + k] * A1[(Hh + k) * Hh + h] + ms[k] * A1[(2 * Hh + k) * Hh + h];
    g_bias1[b * Hh + h] = acc;
}

__global__ void k_scores(const float* __restrict__ A3, const float* __restrict__ ab3) {
    int b = blockIdx.y;
    int i = blockIdx.x * 256 + threadIdx.x;
    float acc = ab3[0];
    const __half* col = g_a2 + (size_t)b * Hh * Nn + i;
    for (int h = 0; h < Hh; h++) acc += __half2float(col[(size_t)h * Nn]) * A3[h];
    g_scores[b * Nn + i] = 10.f * acc;
}

__global__ void k_final(const int* __restrict__ cand, const int* __restrict__ action,
                        const float* __restrict__ C1, const float* __restrict__ cb1,
                        const float* __restrict__ C2, const float* __restrict__ cb2,
                        float* __restrict__ out)
{
    int b = blockIdx.x, tid = threadIdx.x;
    __shared__ float sv[Nn];
    __shared__ float red[256];
    const float* sc = g_scores + b * Nn;
    const int* cd = cand + b * Nn;
    // softmax(scores)
    float mx = -3.4e38f;
    for (int i = tid; i < Nn; i += 256) mx = fmaxf(mx, sc[i]);
    red[tid] = mx; __syncthreads();
    for (int s = 128; s > 0; s >>= 1) { if (tid < s) red[tid] = fmaxf(red[tid], red[tid + s]); __syncthreads(); }
    float smax = red[0]; __syncthreads();
    float sum = 0.f;
    for (int i = tid; i < Nn; i += 256) { float e = expf(sc[i] - smax); sv[i] = e; sum += e; }
    red[tid] = sum; __syncthreads();
    for (int s = 128; s > 0; s >>= 1) { if (tid < s) red[tid] += red[tid + s]; __syncthreads(); }
    float tot = red[0]; __syncthreads();
    // logits = cand ? probs : -1e9 ; log_softmax
    float m2 = -3.4e38f;
    for (int i = tid; i < Nn; i += 256) {
        float z = cd[i] ? (sv[i] / tot) : -1e9f;
        sv[i] = z; m2 = fmaxf(m2, z);
    }
    red[tid] = m2; __syncthreads();
    for (int s = 128; s > 0; s >>= 1) { if (tid < s) red[tid] = fmaxf(red[tid], red[tid + s]); __syncthreads(); }
    m2 = red[0]; __syncthreads();
    float se = 0.f;
    for (int i = tid; i < Nn; i += 256) se += expf(sv[i] - m2);
    red[tid] = se; __syncthreads();
    for (int s = 128; s > 0; s >>= 1) { if (tid < s) red[tid] += red[tid + s]; __syncthreads(); }
    float lse = logf(red[0]); __syncthreads();
    float ent = 0.f;
    for (int i = tid; i < Nn; i += 256) { float lp = sv[i] - m2 - lse; float p = expf(lp); ent -= p * lp; }
    red[tid] = ent; __syncthreads();
    for (int s = 128; s > 0; s >>= 1) { if (tid < s) red[tid] += red[tid + s]; __syncthreads(); }
    float entropy = red[0];
    if (tid == 0) {
        int a = action[b];
        out[b]       = (float)a;
        out[16 + b]  = sv[a] - m2 - lse;
        out[32 + b]  = entropy;
    }
    // critic value from pool
    if (tid < 32) {
        float acc = cb1[tid];
        for (int h = 0; h < Hh; h++) acc += g_pool[b * Hh + h] * C1[h * 32 + tid];
        float r = fmaxf(acc, 0.f) * C2[tid];
#pragma unroll
        for (int o = 16; o > 0; o >>= 1) r += __shfl_down_sync(0xffffffff, r, o);
        if (tid == 0) out[48 + b] = r + cb2[0];
    }
}

// ---------------- launch ----------------
extern "C" void kernel_launch(void* const* d_in, const int* in_sizes, int n_in,
                              void* d_out, int out_size) {
    const float* features = (const float*)d_in[0];
    const int*   adj      = (const int*)d_in[1];
    const int*   cand     = (const int*)d_in[2];
    const int*   action   = (const int*)d_in[3];
    const float* W1  = (const float*)d_in[4];
    const float* b1  = (const float*)d_in[5];
    const float* W2  = (const float*)d_in[6];
    const float* b2  = (const float*)d_in[7];
    const float* W3  = (const float*)d_in[8];
    const float* b3  = (const float*)d_in[9];
    const float* ms  = (const float*)d_in[10];
    const float* A1  = (const float*)d_in[11];
    const float* ab1 = (const float*)d_in[12];
    const float* A2  = (const float*)d_in[13];
    const float* ab2 = (const float*)d_in[14];
    const float* A3  = (const float*)d_in[15];
    const float* ab3 = (const float*)d_in[16];
    const float* C1  = (const float*)d_in[17];
    const float* cb1 = (const float*)d_in[18];
    const float* C2  = (const float*)d_in[19];
    const float* cb2 = (const float*)d_in[20];
    float* out = (float*)d_out;

    void *pAh, *pdeg, *pdis, *pXs, *ph, *pa1, *pa2, *pw16, *pbias1;
    cudaGetSymbolAddress(&pAh,  g_Ah);
    cudaGetSymbolAddress(&pdeg, g_deg);
    cudaGetSymbolAddress(&pdis, g_dis);
    cudaGetSymbolAddress(&pXs,  g_Xs);
    cudaGetSymbolAddress(&ph,   g_h);
    cudaGetSymbolAddress(&pa1,  g_a1);
    cudaGetSymbolAddress(&pa2,  g_a2);
    cudaGetSymbolAddress(&pw16, g_w16);
    cudaGetSymbolAddress(&pbias1, g_bias1);

    __half* Ah   = (__half*)pAh;
    __half* Xs   = (__half*)pXs;
    __half* Hbuf = (__half*)ph;
    __half* A1b  = (__half*)pa1;
    __half* A2b  = (__half*)pa2;
    __half* W16  = (__half*)pw16;
    float*  dis  = (float*)pdis;
    float*  bias1 = (float*)pbias1;

    const size_t sX  = (size_t)Hh * Nn;    // per-batch stride of HxN buffers
    const size_t sAh = (size_t)Nn * Nn;

    cudaMemsetAsync(pdeg, 0, Bb * Nn * sizeof(float));
    k_deg_convert<<<dim3(32, Bb), 256>>>(adj);
    k_dis<<<(Bb * Nn) / 256, 256>>>();
    k_convw<<<(Hh * Hh) / 256, 256>>>(W2, W3, A1, A2);
    k_xs1<<<dim3(Nn / 256, Hh, Bb), 256>>>(features, W1);

    dim3 ggrid(Nn / BN, Bb);
    const int SMEM = 40960;
    // layer 1: big GEMM  hT = relu(dis ⊙ (Ah^T-applied) + b1)
    k_gemm<<<ggrid, 128, SMEM>>>(Xs, Nn, 0, sX, Ah, sAh, Hbuf, sX, Nn, dis, b1, nullptr, 1);
    // layer 2: XsT = dis ⊙ (W2^T hT)
    k_gemm<<<ggrid, 128, SMEM>>>(W16, Hh, 1, 0, Hbuf, sX, Xs, sX, Hh, dis, nullptr, nullptr, 0);
    k_gemm<<<ggrid, 128, SMEM>>>(Xs, Nn, 0, sX, Ah, sAh, Hbuf, sX, Nn, dis, b2, nullptr, 1);
    // layer 3
    k_gemm<<<ggrid, 128, SMEM>>>(W16 + Hh * Hh, Hh, 1, 0, Hbuf, sX, Xs, sX, Hh, dis, nullptr, nullptr, 0);
    k_gemm<<<ggrid, 128, SMEM>>>(Xs, Nn, 0, sX, Ah, sAh, Hbuf, sX, Nn, dis, b3, nullptr, 1);
    // pool + actor bias
    k_pool<<<dim3(Hh / 8, Bb), 256>>>();
    k_bias1<<<Bb, Hh>>>(A1, ab1, ms);
    // actor MLP
    k_gemm<<<ggrid, 128, SMEM>>>(W16 + 2 * Hh * Hh, Hh, 1, 0, Hbuf, sX, A1b, sX, Hh,
                                 nullptr, nullptr, bias1, 1);
    k_gemm<<<ggrid, 128, SMEM>>>(W16 + 3 * Hh * Hh, Hh, 1, 0, A1b, sX, A2b, sX, Hh,
                                 nullptr, ab2, nullptr, 1);
    k_scores<<<dim3(Nn / 256, Bb), 256>>>(A3, ab3);
    k_final<<<Bb, 256>>>(cand, action, C1, cb1, C2, cb2, out);
}

// round 4
// speedup vs baseline: 1.4782x; 1.4782x over previous
#include <cuda_runtime.h>
#include <cuda_fp16.h>
#include <mma.h>
#include <cstdint>
using namespace nvcuda;

#define Bb 16
#define Nn 2048
#define Hh 128

// ---------------- scratch (device globals) ----------------
__device__ __half g_Ah[(size_t)Bb * Nn * Nn];      // adj fp16 + self loops, [b][j][i]
__device__ float  g_deg[Bb * Nn];
__device__ float  g_dis[Bb * Nn];
__device__ __half g_Xs[(size_t)Bb * Hh * Nn];      // [b][h][j]
__device__ __half g_h [(size_t)Bb * Hh * Nn];
__device__ __half g_a1[(size_t)Bb * Hh * Nn];
__device__ __half g_a2[(size_t)Bb * Hh * Nn];
__device__ __half g_w16[4 * Hh * Hh];              // W2^T, W3^T, A1low^T, A2^T (row-major MxK)
__device__ float  g_pool[Bb * Hh];
__device__ float  g_bias1[Bb * Hh];
__device__ float  g_scores[Bb * Nn];

// ---------------- cp.async helpers ----------------
__device__ __forceinline__ uint32_t smem_u32(const void* p) {
    uint32_t a;
    asm("{ .reg .u64 t; cvta.to.shared.u64 t, %1; cvt.u32.u64 %0, t; }" : "=r"(a) : "l"(p));
    return a;
}
__device__ __forceinline__ void cp16(uint32_t s, const void* g) {
    asm volatile("cp.async.cg.shared.global [%0], [%1], 16;" :: "r"(s), "l"(g));
}
#define CP_COMMIT() asm volatile("cp.async.commit_group;" ::: "memory")
#define CP_WAIT(n)  asm volatile("cp.async.wait_group %0;" :: "n"(n) : "memory")

// ---------------- degree + fp16 conversion (fused pass over adj) ----------------
__global__ void k_deg_convert(const int* __restrict__ adj) {
    int b  = blockIdx.y;
    int j0 = blockIdx.x * 64;
    int tid = threadIdx.x;
    float sum[8];
#pragma unroll
    for (int s = 0; s < 8; s++) sum[s] = 0.f;
    const int*  base  = adj  + ((size_t)b * Nn + j0) * Nn;
    __half*     obase = g_Ah + ((size_t)b * Nn + j0) * Nn;
    for (int r = 0; r < 64; r++) {
        int j = j0 + r;
        const int* row = base + (size_t)r * Nn;
        __half* orow = obase + (size_t)r * Nn;
#pragma unroll
        for (int s = 0; s < 8; s++) {
            int c = tid + s * 256;
            int v = row[c];
            float a = (v != 0 || j == c) ? 1.f : 0.f;
            orow[c] = __float2half(a);
            sum[s] += a;
        }
    }
#pragma unroll
    for (int s = 0; s < 8; s++) atomicAdd(&g_deg[b * Nn + tid + s * 256], sum[s]);
}

__global__ void k_dis() {
    int i = blockIdx.x * 256 + threadIdx.x;
    g_dis[i] = rsqrtf(g_deg[i]);
}

// transpose+convert weight blocks: g_w16 row-major [m][k] = W[k][m]
__global__ void k_convw(const float* __restrict__ W2, const float* __restrict__ W3,
                        const float* __restrict__ A1, const float* __restrict__ A2) {
    int i = blockIdx.x * 256 + threadIdx.x;          // 16384
    int r = i >> 7, c = i & 127;
    int t = c * 128 + r;
    g_w16[i]               = __float2half(W2[t]);
    g_w16[Hh * Hh + i]     = __float2half(W3[t]);
    g_w16[2 * Hh * Hh + i] = __float2half(A1[t]);   // first 128 rows of (384,128)
    g_w16[3 * Hh * Hh + i] = __float2half(A2[t]);
}

// Xs1[b][h][j] = dis[j] * (f[j,0]*W1[0,h] + f[j,1]*W1[1,h]) — smem staged, coalesced
__global__ void k_xs1(const float* __restrict__ f, const float* __restrict__ W1) {
    int b = blockIdx.y, j0 = blockIdx.x * 128;
    int tid = threadIdx.x;
    __shared__ float sf0[128], sf1[128], sd[128], sw[256];
    if (tid < 128) {
        int j = j0 + tid;
        sf0[tid] = f[((size_t)b * Nn + j) * 2];
        sf1[tid] = f[((size_t)b * Nn + j) * 2 + 1];
        sd[tid]  = g_dis[b * Nn + j];
    }
    sw[tid] = W1[tid];
    __syncthreads();
#pragma unroll
    for (int t = 0; t < 64; t++) {
        int idx = t * 256 + tid;
        int h = idx >> 7, j = idx & 127;
        float v = sd[j] * (sf0[j] * sw[h] + sf1[j] * sw[128 + h]);
        g_Xs[((size_t)b * Hh + h) * Nn + j0 + j] = __float2half(v);
    }
}

// ---------------- WMMA GEMM: C(128 x 128tile) = A(128 x K) * B(K x Ntile) ----------------
// 8 warps, 128x128x64 tiles, double-buffered cp.async.
#define BM 128
#define BN 128
#define BK 64
#define LDA_S 72
#define LDB_S 136
#define LDC_S 136
#define A_ST (BM * LDA_S)          // halves
#define B_ST (BK * LDB_S)
#define STAGE_H (A_ST + B_ST)
#define GEMM_SMEM (2 * STAGE_H * 2)  // bytes = 71680

__global__ void __launch_bounds__(256) k_gemm(
    const __half* __restrict__ gA, size_t sA, int lda,
    const __half* __restrict__ gB, size_t sB, int ldb,
    __half* __restrict__ gC, size_t sC, int K,
    const float* __restrict__ cscale,   // per (b, n) column scale or null
    const float* __restrict__ rbias,    // [128] row bias or null
    const float* __restrict__ brbias,   // [b*128+m] per-batch row bias or null
    int doRelu)
{
    extern __shared__ char smem[];
    __half* S = (__half*)smem;
    uint32_t sb32 = smem_u32(smem);
    int tid = threadIdx.x, warp = tid >> 5;
    int wm = warp >> 2, wn = warp & 3;            // 2 x 4 warp grid
    int b = blockIdx.y, n0 = blockIdx.x * BN;
    const __half* A  = gA + (size_t)b * sA;
    const __half* Bp = gB + (size_t)b * sB;

    wmma::fragment<wmma::accumulator, 16, 16, 16, float> acc[4][2];
#pragma unroll
    for (int i = 0; i < 4; i++)
#pragma unroll
        for (int j = 0; j < 2; j++) wmma::fill_fragment(acc[i][j], 0.f);

    // stage loader
    auto load_stage = [&](int st, int k0) {
        uint32_t as = sb32 + st * STAGE_H * 2;
        uint32_t bs = as + A_ST * 2;
#pragma unroll
        for (int t = 0; t < 4; t++) {
            int c = tid + t * 256;
            int ar = c >> 3, ak = (c & 7) << 3;
            cp16(as + (ar * LDA_S + ak) * 2, A + (size_t)ar * lda + k0 + ak);
        }
#pragma unroll
        for (int t = 0; t < 4; t++) {
            int c = tid + t * 256;
            int br = c >> 4, bn = (c & 15) << 3;
            cp16(bs + (br * LDB_S + bn) * 2, Bp + (size_t)(k0 + br) * ldb + n0 + bn);
        }
    };

    int KI = K >> 6;
    load_stage(0, 0);
    CP_COMMIT();

    for (int i = 0; i < KI; i++) {
        if (i + 1 < KI) {
            load_stage((i + 1) & 1, (i + 1) * BK);
            CP_COMMIT();
            CP_WAIT(1);
        } else {
            CP_WAIT(0);
        }
        __syncthreads();
        const __half* As = S + (i & 1) * STAGE_H;
        const __half* Bs = As + A_ST;
#pragma unroll
        for (int kk = 0; kk < BK; kk += 16) {
            wmma::fragment<wmma::matrix_a, 16, 16, 16, __half, wmma::row_major> af[4];
            wmma::fragment<wmma::matrix_b, 16, 16, 16, __half, wmma::row_major> bf[2];
#pragma unroll
            for (int x = 0; x < 4; x++)
                wmma::load_matrix_sync(af[x], As + (wm * 64 + x * 16) * LDA_S + kk, LDA_S);
#pragma unroll
            for (int y = 0; y < 2; y++)
                wmma::load_matrix_sync(bf[y], Bs + kk * LDB_S + wn * 32 + y * 16, LDB_S);
#pragma unroll
            for (int x = 0; x < 4; x++)
#pragma unroll
                for (int y = 0; y < 2; y++)
                    wmma::mma_sync(acc[x][y], af[x], bf[y], acc[x][y]);
        }
        __syncthreads();
    }

    // epilogue: stage fp32 in smem, then fused scale/bias/relu + vectorized store
    float* Cs = (float*)smem;
#pragma unroll
    for (int x = 0; x < 4; x++)
#pragma unroll
        for (int y = 0; y < 2; y++)
            wmma::store_matrix_sync(Cs + (wm * 64 + x * 16) * LDC_S + wn * 32 + y * 16,
                                    acc[x][y], LDC_S, wmma::mem_row_major);
    __syncthreads();
    const float* cs = cscale ? cscale + (size_t)b * Nn + n0 : nullptr;
    const float* bbp = brbias ? brbias + b * Hh : nullptr;
#pragma unroll
    for (int t = 0; t < 8; t++) {
        int c = tid + t * 256;           // 2048 chunks of 8 halves
        int m = c >> 4, nc = (c & 15) << 3;
        float rbv = 0.f;
        if (rbias) rbv += rbias[m];
        if (bbp)   rbv += bbp[m];
        __half2 hb[4];
#pragma unroll
        for (int e = 0; e < 8; e += 2) {
            float v0 = Cs[m * LDC_S + nc + e];
            float v1 = Cs[m * LDC_S + nc + e + 1];
            if (cs) { v0 *= cs[nc + e]; v1 *= cs[nc + e + 1]; }
            v0 += rbv; v1 += rbv;
            if (doRelu) { v0 = fmaxf(v0, 0.f); v1 = fmaxf(v1, 0.f); }
            hb[e >> 1] = __floats2half2_rn(v0, v1);
        }
        *(uint4*)(gC + (size_t)b * sC + (size_t)m * Nn + n0 + nc) = *(const uint4*)hb;
    }
}

// ---------------- pool, actor bias, scores, finals ----------------
__global__ void k_pool() {
    int b = blockIdx.y;
    int warp = threadIdx.x / 32, lane = threadIdx.x % 32;
    int h = blockIdx.x * 8 + warp;
    const __half* row = g_h + ((size_t)b * Hh + h) * Nn;
    float s = 0.f;
    for (int i = lane; i < Nn; i += 32) s += __half2float(row[i]);
#pragma unroll
    for (int o = 16; o > 0; o >>= 1) s += __shfl_down_sync(0xffffffff, s, o);
    if (lane == 0) g_pool[b * Hh + h] = s / (float)Nn;
}

__global__ void k_bias1(const float* __restrict__ A1, const float* __restrict__ ab1,
                        const float* __restrict__ ms) {
    int b = blockIdx.x, h = threadIdx.x;
    float acc = ab1[h];
    for (int k = 0; k < Hh; k++)
        acc += g_pool[b * Hh + k] * A1[(Hh + k) * Hh + h] + ms[k] * A1[(2 * Hh + k) * Hh + h];
    g_bias1[b * Hh + h] = acc;
}

__global__ void k_scores(const float* __restrict__ A3, const float* __restrict__ ab3) {
    int b = blockIdx.y;
    int i = blockIdx.x * 256 + threadIdx.x;
    float acc = ab3[0];
    const __half* col = g_a2 + (size_t)b * Hh * Nn + i;
    for (int h = 0; h < Hh; h++) acc += __half2float(col[(size_t)h * Nn]) * A3[h];
    g_scores[b * Nn + i] = 10.f * acc;
}

__global__ void k_final(const int* __restrict__ cand, const int* __restrict__ action,
                        const float* __restrict__ C1, const float* __restrict__ cb1,
                        const float* __restrict__ C2, const float* __restrict__ cb2,
                        float* __restrict__ out)
{
    int b = blockIdx.x, tid = threadIdx.x;
    __shared__ float sv[Nn];
    __shared__ float red[256];
    const float* sc = g_scores + b * Nn;
    const int* cd = cand + b * Nn;
    float mx = -3.4e38f;
    for (int i = tid; i < Nn; i += 256) mx = fmaxf(mx, sc[i]);
    red[tid] = mx; __syncthreads();
    for (int s = 128; s > 0; s >>= 1) { if (tid < s) red[tid] = fmaxf(red[tid], red[tid + s]); __syncthreads(); }
    float smax = red[0]; __syncthreads();
    float sum = 0.f;
    for (int i = tid; i < Nn; i += 256) { float e = expf(sc[i] - smax); sv[i] = e; sum += e; }
    red[tid] = sum; __syncthreads();
    for (int s = 128; s > 0; s >>= 1) { if (tid < s) red[tid] += red[tid + s]; __syncthreads(); }
    float tot = red[0]; __syncthreads();
    float m2 = -3.4e38f;
    for (int i = tid; i < Nn; i += 256) {
        float z = cd[i] ? (sv[i] / tot) : -1e9f;
        sv[i] = z; m2 = fmaxf(m2, z);
    }
    red[tid] = m2; __syncthreads();
    for (int s = 128; s > 0; s >>= 1) { if (tid < s) red[tid] = fmaxf(red[tid], red[tid + s]); __syncthreads(); }
    m2 = red[0]; __syncthreads();
    float se = 0.f;
    for (int i = tid; i < Nn; i += 256) se += expf(sv[i] - m2);
    red[tid] = se; __syncthreads();
    for (int s = 128; s > 0; s >>= 1) { if (tid < s) red[tid] += red[tid + s]; __syncthreads(); }
    float lse = logf(red[0]); __syncthreads();
    float ent = 0.f;
    for (int i = tid; i < Nn; i += 256) { float lp = sv[i] - m2 - lse; float p = expf(lp); ent -= p * lp; }
    red[tid] = ent; __syncthreads();
    for (int s = 128; s > 0; s >>= 1) { if (tid < s) red[tid] += red[tid + s]; __syncthreads(); }
    float entropy = red[0];
    if (tid == 0) {
        int a = action[b];
        out[b]       = (float)a;
        out[16 + b]  = sv[a] - m2 - lse;
        out[32 + b]  = entropy;
    }
    if (tid < 32) {
        float acc = cb1[tid];
        for (int h = 0; h < Hh; h++) acc += g_pool[b * Hh + h] * C1[h * 32 + tid];
        float r = fmaxf(acc, 0.f) * C2[tid];
#pragma unroll
        for (int o = 16; o > 0; o >>= 1) r += __shfl_down_sync(0xffffffff, r, o);
        if (tid == 0) out[48 + b] = r + cb2[0];
    }
}

// ---------------- launch ----------------
extern "C" void kernel_launch(void* const* d_in, const int* in_sizes, int n_in,
                              void* d_out, int out_size) {
    const float* features = (const float*)d_in[0];
    const int*   adj      = (const int*)d_in[1];
    const int*   cand     = (const int*)d_in[2];
    const int*   action   = (const int*)d_in[3];
    const float* W1  = (const float*)d_in[4];
    const float* b1  = (const float*)d_in[5];
    const float* W2  = (const float*)d_in[6];
    const float* b2  = (const float*)d_in[7];
    const float* W3  = (const float*)d_in[8];
    const float* b3  = (const float*)d_in[9];
    const float* ms  = (const float*)d_in[10];
    const float* A1  = (const float*)d_in[11];
    const float* ab1 = (const float*)d_in[12];
    const float* A2  = (const float*)d_in[13];
    const float* ab2 = (const float*)d_in[14];
    const float* A3  = (const float*)d_in[15];
    const float* ab3 = (const float*)d_in[16];
    const float* C1  = (const float*)d_in[17];
    const float* cb1 = (const float*)d_in[18];
    const float* C2  = (const float*)d_in[19];
    const float* cb2 = (const float*)d_in[20];
    float* out = (float*)d_out;

    void *pAh, *pdeg, *pdis, *pXs, *ph, *pa1, *pa2, *pw16, *pbias1;
    cudaGetSymbolAddress(&pAh,  g_Ah);
    cudaGetSymbolAddress(&pdeg, g_deg);
    cudaGetSymbolAddress(&pdis, g_dis);
    cudaGetSymbolAddress(&pXs,  g_Xs);
    cudaGetSymbolAddress(&ph,   g_h);
    cudaGetSymbolAddress(&pa1,  g_a1);
    cudaGetSymbolAddress(&pa2,  g_a2);
    cudaGetSymbolAddress(&pw16, g_w16);
    cudaGetSymbolAddress(&pbias1, g_bias1);

    __half* Ah   = (__half*)pAh;
    __half* Xs   = (__half*)pXs;
    __half* Hbuf = (__half*)ph;
    __half* A1b  = (__half*)pa1;
    __half* A2b  = (__half*)pa2;
    __half* W16  = (__half*)pw16;
    float*  dis  = (float*)pdis;
    float*  bias1 = (float*)pbias1;

    const size_t HN = (size_t)Hh * Nn;
    const size_t NN = (size_t)Nn * Nn;

    cudaFuncSetAttribute(k_gemm, cudaFuncAttributeMaxDynamicSharedMemorySize, GEMM_SMEM);

    cudaMemsetAsync(pdeg, 0, Bb * Nn * sizeof(float));
    k_deg_convert<<<dim3(32, Bb), 256>>>(adj);
    k_dis<<<(Bb * Nn) / 256, 256>>>();
    k_convw<<<(Hh * Hh) / 256, 256>>>(W2, W3, A1, A2);
    k_xs1<<<dim3(16, Bb), 256>>>(features, W1);

    dim3 gg(Nn / BN, Bb);
    // layer 1 aggregation: h[h][i] = relu(dis_i * Σ_j Xs[h][j] Ah[j][i] + b1[h])
    k_gemm<<<gg, 256, GEMM_SMEM>>>(Xs, HN, Nn, Ah, NN, Nn, Hbuf, HN, Nn, dis, b1, nullptr, 1);
    // layer 2 projection: Xs2[h'][j] = dis_j * Σ_h W2T[h'][h] h[h][j]
    k_gemm<<<gg, 256, GEMM_SMEM>>>(W16, 0, Hh, Hbuf, HN, Nn, Xs, HN, Hh, dis, nullptr, nullptr, 0);
    k_gemm<<<gg, 256, GEMM_SMEM>>>(Xs, HN, Nn, Ah, NN, Nn, Hbuf, HN, Nn, dis, b2, nullptr, 1);
    // layer 3
    k_gemm<<<gg, 256, GEMM_SMEM>>>(W16 + Hh * Hh, 0, Hh, Hbuf, HN, Nn, Xs, HN, Hh, dis, nullptr, nullptr, 0);
    k_gemm<<<gg, 256, GEMM_SMEM>>>(Xs, HN, Nn, Ah, NN, Nn, Hbuf, HN, Nn, dis, b3, nullptr, 1);
    // pool + actor bias
    k_pool<<<dim3(Hh / 8, Bb), 256>>>();
    k_bias1<<<Bb, Hh>>>(A1, ab1, ms);
    // actor MLP
    k_gemm<<<gg, 256, GEMM_SMEM>>>(W16 + 2 * Hh * Hh, 0, Hh, Hbuf, HN, Nn, A1b, HN, Hh,
                                   nullptr, nullptr, bias1, 1);
    k_gemm<<<gg, 256, GEMM_SMEM>>>(W16 + 3 * Hh * Hh, 0, Hh, A1b, HN, Nn, A2b, HN, Hh,
                                   nullptr, ab2, nullptr, 1);
    k_scores<<<dim3(Nn / 256, Bb), 256>>>(A3, ab3);
    k_final<<<Bb, 256>>>(cand, action, C1, cb1, C2, cb2, out);
}

// round 5
// speedup vs baseline: 1.5019x; 1.0161x over previous
#include <cuda_runtime.h>
#include <cuda_fp16.h>
#include <mma.h>
#include <cstdint>
using namespace nvcuda;

#define Bb 16
#define Nn 2048
#define Hh 128

// ---------------- scratch ----------------
__device__ __half g_Ah[(size_t)Bb * Nn * Nn];      // adj fp16 + self loops, [b][j][i]
__device__ float  g_deg[Bb * Nn];
__device__ float  g_dis[Bb * Nn];
__device__ __half g_Xs[(size_t)Bb * Hh * Nn];      // [b][h][j]
__device__ __half g_h [(size_t)Bb * Hh * Nn];
__device__ __half g_a1[(size_t)Bb * Hh * Nn];
__device__ __half g_w16[4 * Hh * Hh];              // W2^T, W3^T, A1low^T, A2^T (row-major MxK)
__device__ float  g_pool[Bb * Hh];                 // raw sums (x2048)
__device__ float  g_bias1[Bb * Hh];
__device__ float  g_scores[Bb * Nn];

// ---------------- helpers ----------------
__device__ __forceinline__ uint32_t smem_u32(const void* p) {
    uint32_t a;
    asm("{ .reg .u64 t; cvta.to.shared.u64 t, %1; cvt.u32.u64 %0, t; }" : "=r"(a) : "l"(p));
    return a;
}
__device__ __forceinline__ void cp16(uint32_t s, const void* g) {
    asm volatile("cp.async.cg.shared.global [%0], [%1], 16;" :: "r"(s), "l"(g));
}
#define CP_COMMIT() asm volatile("cp.async.commit_group;" ::: "memory")
#define CP_WAIT(n)  asm volatile("cp.async.wait_group %0;" :: "n"(n) : "memory")

// ---------------- degree + fp16 conversion ----------------
__global__ void k_deg_convert(const int* __restrict__ adj) {
    int b  = blockIdx.y;
    int j0 = blockIdx.x * 64;
    int tid = threadIdx.x;
    float sum[8];
#pragma unroll
    for (int s = 0; s < 8; s++) sum[s] = 0.f;
    const int*  base  = adj  + ((size_t)b * Nn + j0) * Nn;
    __half*     obase = g_Ah + ((size_t)b * Nn + j0) * Nn;
    for (int r = 0; r < 64; r++) {
        int j = j0 + r;
        const int* row = base + (size_t)r * Nn;
        __half* orow = obase + (size_t)r * Nn;
#pragma unroll
        for (int s = 0; s < 8; s++) {
            int c = tid + s * 256;
            int v = row[c];
            float a = (v != 0 || j == c) ? 1.f : 0.f;
            orow[c] = __float2half(a);
            sum[s] += a;
        }
    }
#pragma unroll
    for (int s = 0; s < 8; s++) atomicAdd(&g_deg[b * Nn + tid + s * 256], sum[s]);
}

__global__ void k_dis() {
    int i = blockIdx.x * 256 + threadIdx.x;
    g_dis[i] = rsqrtf(g_deg[i]);
}

__global__ void k_convw(const float* __restrict__ W2, const float* __restrict__ W3,
                        const float* __restrict__ A1, const float* __restrict__ A2) {
    int i = blockIdx.x * 256 + threadIdx.x;
    int r = i >> 7, c = i & 127;
    int t = c * 128 + r;
    g_w16[i]               = __float2half(W2[t]);
    g_w16[Hh * Hh + i]     = __float2half(W3[t]);
    g_w16[2 * Hh * Hh + i] = __float2half(A1[t]);
    g_w16[3 * Hh * Hh + i] = __float2half(A2[t]);
}

__global__ void k_xs1(const float* __restrict__ f, const float* __restrict__ W1) {
    int b = blockIdx.y, j0 = blockIdx.x * 128;
    int tid = threadIdx.x;
    __shared__ float sf0[128], sf1[128], sd[128], sw[256];
    if (tid < 128) {
        int j = j0 + tid;
        sf0[tid] = f[((size_t)b * Nn + j) * 2];
        sf1[tid] = f[((size_t)b * Nn + j) * 2 + 1];
        sd[tid]  = g_dis[b * Nn + j];
    }
    sw[tid] = W1[tid];
    __syncthreads();
#pragma unroll
    for (int t = 0; t < 32; t++) {
        int idx = t * 256 + tid;                 // (h, j-pair)
        int h = idx >> 6, jp = (idx & 63) << 1;
        float v0 = sd[jp]     * (sf0[jp]     * sw[h] + sf1[jp]     * sw[128 + h]);
        float v1 = sd[jp + 1] * (sf0[jp + 1] * sw[h] + sf1[jp + 1] * sw[128 + h]);
        *(__half2*)(g_Xs + ((size_t)b * Hh + h) * Nn + j0 + jp) = __floats2half2_rn(v0, v1);
    }
}

// ---------------- WMMA GEMM: C(128 x 256tile) = A(128 x K) * B(K x Ntile) ----------------
// 8 warps (2x4), warp tile 64x64, BK=64, 3-stage cp.async pipeline.
#define BM 128
#define BN 256
#define BK 64
#define LDA_S 72
#define LDB_S 264
#define LDC_S 264
#define A_ST (BM * LDA_S)
#define B_ST (BK * LDB_S)
#define STAGE_H (A_ST + B_ST)
#define GEMM_SMEM (3 * STAGE_H * 2)   // 156672 B

// outMode: 0 = store C fp16; 1 = store C + pool atomics; 2 = scores only (no C store)
__global__ void __launch_bounds__(256) k_gemm(
    const __half* __restrict__ gA, size_t sA, int lda,
    const __half* __restrict__ gB, size_t sB, int ldb,
    __half* __restrict__ gC, size_t sC, int K,
    const float* __restrict__ cscale, const float* __restrict__ rbias,
    const float* __restrict__ brbias, int doRelu, int outMode,
    const float* __restrict__ pA3, const float* __restrict__ pab3,
    float* __restrict__ poolOut, float* __restrict__ scoresOut)
{
    extern __shared__ char smem[];
    __half* S = (__half*)smem;
    uint32_t sb32 = smem_u32(smem);
    int tid = threadIdx.x, warp = tid >> 5;
    int wm = warp >> 2, wn = warp & 3;
    int b = blockIdx.y, n0 = blockIdx.x * BN;
    const __half* A  = gA + (size_t)b * sA;
    const __half* Bp = gB + (size_t)b * sB;

    wmma::fragment<wmma::accumulator, 16, 16, 16, float> acc[4][4];
#pragma unroll
    for (int i = 0; i < 4; i++)
#pragma unroll
        for (int j = 0; j < 4; j++) wmma::fill_fragment(acc[i][j], 0.f);

    auto load_stage = [&](int st, int k0) {
        uint32_t as = sb32 + st * STAGE_H * 2;
        uint32_t bs = as + A_ST * 2;
#pragma unroll
        for (int t = 0; t < 4; t++) {
            int c = tid + t * 256;
            int ar = c >> 3, ak = (c & 7) << 3;
            cp16(as + (ar * LDA_S + ak) * 2, A + (size_t)ar * lda + k0 + ak);
        }
#pragma unroll
        for (int t = 0; t < 8; t++) {
            int c = tid + t * 256;
            int br = c >> 5, bn = (c & 31) << 3;
            cp16(bs + (br * LDB_S + bn) * 2, Bp + (size_t)(k0 + br) * ldb + n0 + bn);
        }
    };

    int KI = K >> 6;
    load_stage(0, 0); CP_COMMIT();
    load_stage(1, BK); CP_COMMIT();

    for (int i = 0; i < KI; i++) {
        if (i < KI - 1) CP_WAIT(1); else CP_WAIT(0);
        __syncthreads();
        if (i + 2 < KI) { load_stage((i + 2) % 3, (i + 2) * BK); CP_COMMIT(); }
        const __half* As = S + (i % 3) * STAGE_H;
        const __half* Bs = As + A_ST;
#pragma unroll
        for (int kk = 0; kk < BK; kk += 16) {
            wmma::fragment<wmma::matrix_a, 16, 16, 16, __half, wmma::row_major> af[4];
            wmma::fragment<wmma::matrix_b, 16, 16, 16, __half, wmma::row_major> bf[4];
#pragma unroll
            for (int x = 0; x < 4; x++)
                wmma::load_matrix_sync(af[x], As + (wm * 64 + x * 16) * LDA_S + kk, LDA_S);
#pragma unroll
            for (int y = 0; y < 4; y++)
                wmma::load_matrix_sync(bf[y], Bs + kk * LDB_S + wn * 64 + y * 16, LDB_S);
#pragma unroll
            for (int x = 0; x < 4; x++)
#pragma unroll
                for (int y = 0; y < 4; y++)
                    wmma::mma_sync(acc[x][y], af[x], bf[y], acc[x][y]);
        }
    }
    __syncthreads();

    float* Cs = (float*)smem;
#pragma unroll
    for (int x = 0; x < 4; x++)
#pragma unroll
        for (int y = 0; y < 4; y++)
            wmma::store_matrix_sync(Cs + (wm * 64 + x * 16) * LDC_S + wn * 64 + y * 16,
                                    acc[x][y], LDC_S, wmma::mem_row_major);
    __syncthreads();

    if (outMode == 2) {
        // scores: per-column reduction over m with relu(acc + ab2[m]) * A3[m]
        float* sA3 = (float*)(smem + BM * LDC_S * 4);
        float* sbv = sA3 + 128;
        if (tid < 128) { sA3[tid] = pA3[tid]; sbv[tid] = rbias[tid]; }
        __syncthreads();
        int n = tid;                       // 256 threads, 256 cols
        float accv = 0.f;
#pragma unroll 4
        for (int m = 0; m < 128; m++) {
            float v = Cs[m * LDC_S + n] + sbv[m];
            v = fmaxf(v, 0.f);
            accv += v * sA3[m];
        }
        scoresOut[(size_t)b * Nn + n0 + n] = 10.f * (accv + pab3[0]);
        return;
    }

    const float* cs = cscale ? cscale + (size_t)b * Nn + n0 : nullptr;
    const float* bbp = brbias ? brbias + b * Hh : nullptr;
#pragma unroll
    for (int t = 0; t < 16; t++) {
        int c = tid + t * 256;                   // 4096 chunks of 8 halves
        int m = c >> 5, nc = (c & 31) << 3;
        float rbv = 0.f;
        if (rbias) rbv += rbias[m];
        if (bbp)   rbv += bbp[m];
        __half2 hb[4];
#pragma unroll
        for (int e = 0; e < 8; e += 2) {
            float v0 = Cs[m * LDC_S + nc + e];
            float v1 = Cs[m * LDC_S + nc + e + 1];
            if (cs) { v0 *= cs[nc + e]; v1 *= cs[nc + e + 1]; }
            v0 += rbv; v1 += rbv;
            if (doRelu) { v0 = fmaxf(v0, 0.f); v1 = fmaxf(v1, 0.f); }
            hb[e >> 1] = __floats2half2_rn(v0, v1);
        }
        *(uint4*)(gC + (size_t)b * sC + (size_t)m * Nn + n0 + nc) = *(const uint4*)hb;
    }
    if (outMode == 1) {
        // pool partial sums: thread t -> row m = t&127, half = t>>7
        int m = tid & 127, hf = tid >> 7;
        float rbv = rbias ? rbias[m] : 0.f;
        float part = 0.f;
#pragma unroll 4
        for (int n = hf * 128; n < hf * 128 + 128; n++) {
            float v = Cs[m * LDC_S + n];
            if (cs) v *= cs[n];
            v += rbv;
            part += fmaxf(v, 0.f);
        }
        atomicAdd(&poolOut[b * Hh + m], part);
    }
}

// ---------------- bias1, final ----------------
__global__ void k_bias1(const float* __restrict__ A1, const float* __restrict__ ab1,
                        const float* __restrict__ ms) {
    int b = blockIdx.x, h = threadIdx.x;
    const float inv = 1.f / 2048.f;
    float acc = ab1[h];
    for (int k = 0; k < Hh; k++)
        acc += g_pool[b * Hh + k] * inv * A1[(Hh + k) * Hh + h] + ms[k] * A1[(2 * Hh + k) * Hh + h];
    g_bias1[b * Hh + h] = acc;
}

__global__ void k_final(const int* __restrict__ cand, const int* __restrict__ action,
                        const float* __restrict__ C1, const float* __restrict__ cb1,
                        const float* __restrict__ C2, const float* __restrict__ cb2,
                        float* __restrict__ out)
{
    int b = blockIdx.x, tid = threadIdx.x;
    __shared__ float sv[Nn];
    __shared__ float red[256];
    const float* sc = g_scores + b * Nn;
    const int* cd = cand + b * Nn;
    float mx = -3.4e38f;
    for (int i = tid; i < Nn; i += 256) mx = fmaxf(mx, sc[i]);
    red[tid] = mx; __syncthreads();
    for (int s = 128; s > 0; s >>= 1) { if (tid < s) red[tid] = fmaxf(red[tid], red[tid + s]); __syncthreads(); }
    float smax = red[0]; __syncthreads();
    float sum = 0.f;
    for (int i = tid; i < Nn; i += 256) { float e = expf(sc[i] - smax); sv[i] = e; sum += e; }
    red[tid] = sum; __syncthreads();
    for (int s = 128; s > 0; s >>= 1) { if (tid < s) red[tid] += red[tid + s]; __syncthreads(); }
    float tot = red[0]; __syncthreads();
    float m2 = -3.4e38f;
    for (int i = tid; i < Nn; i += 256) {
        float z = cd[i] ? (sv[i] / tot) : -1e9f;
        sv[i] = z; m2 = fmaxf(m2, z);
    }
    red[tid] = m2; __syncthreads();
    for (int s = 128; s > 0; s >>= 1) { if (tid < s) red[tid] = fmaxf(red[tid], red[tid + s]); __syncthreads(); }
    m2 = red[0]; __syncthreads();
    float se = 0.f;
    for (int i = tid; i < Nn; i += 256) se += expf(sv[i] - m2);
    red[tid] = se; __syncthreads();
    for (int s = 128; s > 0; s >>= 1) { if (tid < s) red[tid] += red[tid + s]; __syncthreads(); }
    float lse = logf(red[0]); __syncthreads();
    float ent = 0.f;
    for (int i = tid; i < Nn; i += 256) { float lp = sv[i] - m2 - lse; float p = expf(lp); ent -= p * lp; }
    red[tid] = ent; __syncthreads();
    for (int s = 128; s > 0; s >>= 1) { if (tid < s) red[tid] += red[tid + s]; __syncthreads(); }
    float entropy = red[0];
    if (tid == 0) {
        int a = action[b];
        out[b]      = (float)a;
        out[16 + b] = sv[a] - m2 - lse;
        out[32 + b] = entropy;
    }
    if (tid < 32) {
        const float inv = 1.f / 2048.f;
        float acc = cb1[tid];
        for (int h = 0; h < Hh; h++) acc += g_pool[b * Hh + h] * inv * C1[h * 32 + tid];
        float r = fmaxf(acc, 0.f) * C2[tid];
#pragma unroll
        for (int o = 16; o > 0; o >>= 1) r += __shfl_down_sync(0xffffffff, r, o);
        if (tid == 0) out[48 + b] = r + cb2[0];
    }
}

// ---------------- launch ----------------
extern "C" void kernel_launch(void* const* d_in, const int* in_sizes, int n_in,
                              void* d_out, int out_size) {
    const float* features = (const float*)d_in[0];
    const int*   adj      = (const int*)d_in[1];
    const int*   cand     = (const int*)d_in[2];
    const int*   action   = (const int*)d_in[3];
    const float* W1  = (const float*)d_in[4];
    const float* b1  = (const float*)d_in[5];
    const float* W2  = (const float*)d_in[6];
    const float* b2  = (const float*)d_in[7];
    const float* W3  = (const float*)d_in[8];
    const float* b3  = (const float*)d_in[9];
    const float* ms  = (const float*)d_in[10];
    const float* A1  = (const float*)d_in[11];
    const float* ab1 = (const float*)d_in[12];
    const float* A2  = (const float*)d_in[13];
    const float* ab2 = (const float*)d_in[14];
    const float* A3  = (const float*)d_in[15];
    const float* ab3 = (const float*)d_in[16];
    const float* C1  = (const float*)d_in[17];
    const float* cb1 = (const float*)d_in[18];
    const float* C2  = (const float*)d_in[19];
    const float* cb2 = (const float*)d_in[20];
    float* out = (float*)d_out;

    void *pAh, *pdeg, *pdis, *pXs, *ph, *pa1, *pw16, *pbias1, *ppool, *pscores;
    cudaGetSymbolAddress(&pAh,  g_Ah);
    cudaGetSymbolAddress(&pdeg, g_deg);
    cudaGetSymbolAddress(&pdis, g_dis);
    cudaGetSymbolAddress(&pXs,  g_Xs);
    cudaGetSymbolAddress(&ph,   g_h);
    cudaGetSymbolAddress(&pa1,  g_a1);
    cudaGetSymbolAddress(&pw16, g_w16);
    cudaGetSymbolAddress(&pbias1, g_bias1);
    cudaGetSymbolAddress(&ppool, g_pool);
    cudaGetSymbolAddress(&pscores, g_scores);

    __half* Ah   = (__half*)pAh;
    __half* Xs   = (__half*)pXs;
    __half* Hbuf = (__half*)ph;
    __half* A1b  = (__half*)pa1;
    __half* W16  = (__half*)pw16;
    float*  dis  = (float*)pdis;
    float*  bias1 = (float*)pbias1;
    float*  pool = (float*)ppool;
    float*  scores = (float*)pscores;

    const size_t HN = (size_t)Hh * Nn;
    const size_t NN = (size_t)Nn * Nn;

    cudaFuncSetAttribute(k_gemm, cudaFuncAttributeMaxDynamicSharedMemorySize, GEMM_SMEM);

    cudaMemsetAsync(pdeg, 0, Bb * Nn * sizeof(float));
    cudaMemsetAsync(ppool, 0, Bb * Hh * sizeof(float));
    k_deg_convert<<<dim3(32, Bb), 256>>>(adj);
    k_dis<<<(Bb * Nn) / 256, 256>>>();
    k_convw<<<(Hh * Hh) / 256, 256>>>(W2, W3, A1, A2);
    k_xs1<<<dim3(16, Bb), 256>>>(features, W1);

    dim3 gg(Nn / BN, Bb);
    // layer 1: h[h][i] = relu(dis_i * Σ_j Xs[h][j] Ah[j][i] + b1[h])
    k_gemm<<<gg, 256, GEMM_SMEM>>>(Xs, HN, Nn, Ah, NN, Nn, Hbuf, HN, Nn,
                                   dis, b1, nullptr, 1, 0, nullptr, nullptr, nullptr, nullptr);
    // layer 2 projection + aggregation
    k_gemm<<<gg, 256, GEMM_SMEM>>>(W16, 0, Hh, Hbuf, HN, Nn, Xs, HN, Hh,
                                   dis, nullptr, nullptr, 0, 0, nullptr, nullptr, nullptr, nullptr);
    k_gemm<<<gg, 256, GEMM_SMEM>>>(Xs, HN, Nn, Ah, NN, Nn, Hbuf, HN, Nn,
                                   dis, b2, nullptr, 1, 0, nullptr, nullptr, nullptr, nullptr);
    // layer 3 (pool fused into epilogue)
    k_gemm<<<gg, 256, GEMM_SMEM>>>(W16 + Hh * Hh, 0, Hh, Hbuf, HN, Nn, Xs, HN, Hh,
                                   dis, nullptr, nullptr, 0, 0, nullptr, nullptr, nullptr, nullptr);
    k_gemm<<<gg, 256, GEMM_SMEM>>>(Xs, HN, Nn, Ah, NN, Nn, Hbuf, HN, Nn,
                                   dis, b3, nullptr, 1, 1, nullptr, nullptr, pool, nullptr);
    // actor
    k_bias1<<<Bb, Hh>>>(A1, ab1, ms);
    k_gemm<<<gg, 256, GEMM_SMEM>>>(W16 + 2 * Hh * Hh, 0, Hh, Hbuf, HN, Nn, A1b, HN, Hh,
                                   nullptr, nullptr, bias1, 1, 0, nullptr, nullptr, nullptr, nullptr);
    // a2 GEMM with fused scores reduction (no C store)
    k_gemm<<<gg, 256, GEMM_SMEM>>>(W16 + 3 * Hh * Hh, 0, Hh, A1b, HN, Nn, A1b, HN, Hh,
                                   nullptr, ab2, nullptr, 1, 2, A3, ab3, nullptr, scores);
    k_final<<<Bb, 256>>>(cand, action, C1, cb1, C2, cb2, out);
}

// round 6
// speedup vs baseline: 1.5029x; 1.0007x over previous
#include <cuda_runtime.h>
#include <cuda_fp16.h>
#include <mma.h>
#include <cstdint>
using namespace nvcuda;

#define Bb 16
#define Nn 2048
#define Hh 128

// ---------------- scratch ----------------
__device__ __half g_Ah[(size_t)Bb * Nn * Nn];      // adj fp16 + self loops, [b][j][i]
__device__ float  g_deg[Bb * Nn];
__device__ float  g_dis[Bb * Nn];
__device__ __half g_Xs[(size_t)Bb * Hh * Nn];      // [b][h][j]
__device__ __half g_h [(size_t)Bb * Hh * Nn];
__device__ __half g_a1[(size_t)Bb * Hh * Nn];
__device__ __half g_w16[4 * Hh * Hh];              // W2^T, W3^T, A1low^T, A2^T (row-major MxK)
__device__ float  g_pool[Bb * Hh];                 // raw sums (x2048)
__device__ float  g_bias1[Bb * Hh];
__device__ float  g_scores[Bb * Nn];

// ---------------- helpers ----------------
__device__ __forceinline__ uint32_t smem_u32(const void* p) {
    uint32_t a;
    asm("{ .reg .u64 t; cvta.to.shared.u64 t, %1; cvt.u32.u64 %0, t; }" : "=r"(a) : "l"(p));
    return a;
}
__device__ __forceinline__ void cp16(uint32_t s, const void* g) {
    asm volatile("cp.async.cg.shared.global [%0], [%1], 16;" :: "r"(s), "l"(g));
}
#define CP_COMMIT() asm volatile("cp.async.commit_group;" ::: "memory")
#define CP_WAIT(n)  asm volatile("cp.async.wait_group %0;" :: "n"(n) : "memory")

// ---------------- degree + fp16 conversion ----------------
__global__ void k_deg_convert(const int* __restrict__ adj) {
    int b  = blockIdx.y;
    int j0 = blockIdx.x * 64;
    int tid = threadIdx.x;
    float sum[8];
#pragma unroll
    for (int s = 0; s < 8; s++) sum[s] = 0.f;
    const int*  base  = adj  + ((size_t)b * Nn + j0) * Nn;
    __half*     obase = g_Ah + ((size_t)b * Nn + j0) * Nn;
    for (int r = 0; r < 64; r++) {
        int j = j0 + r;
        const int* row = base + (size_t)r * Nn;
        __half* orow = obase + (size_t)r * Nn;
#pragma unroll
        for (int s = 0; s < 8; s++) {
            int c = tid + s * 256;
            int v = row[c];
            float a = (v != 0 || j == c) ? 1.f : 0.f;
            orow[c] = __float2half(a);
            sum[s] += a;
        }
    }
#pragma unroll
    for (int s = 0; s < 8; s++) atomicAdd(&g_deg[b * Nn + tid + s * 256], sum[s]);
}

__global__ void k_dis() {
    int i = blockIdx.x * 256 + threadIdx.x;
    g_dis[i] = rsqrtf(g_deg[i]);
}

__global__ void k_convw(const float* __restrict__ W2, const float* __restrict__ W3,
                        const float* __restrict__ A1, const float* __restrict__ A2) {
    int i = blockIdx.x * 256 + threadIdx.x;
    int r = i >> 7, c = i & 127;
    int t = c * 128 + r;
    g_w16[i]               = __float2half(W2[t]);
    g_w16[Hh * Hh + i]     = __float2half(W3[t]);
    g_w16[2 * Hh * Hh + i] = __float2half(A1[t]);
    g_w16[3 * Hh * Hh + i] = __float2half(A2[t]);
}

__global__ void k_xs1(const float* __restrict__ f, const float* __restrict__ W1) {
    int b = blockIdx.y, j0 = blockIdx.x * 128;
    int tid = threadIdx.x;
    __shared__ float sf0[128], sf1[128], sd[128], sw[256];
    if (tid < 128) {
        int j = j0 + tid;
        sf0[tid] = f[((size_t)b * Nn + j) * 2];
        sf1[tid] = f[((size_t)b * Nn + j) * 2 + 1];
        sd[tid]  = g_dis[b * Nn + j];
    }
    sw[tid] = W1[tid];
    __syncthreads();
#pragma unroll
    for (int t = 0; t < 32; t++) {
        int idx = t * 256 + tid;                 // (h, j-pair)
        int h = idx >> 6, jp = (idx & 63) << 1;
        float v0 = sd[jp]     * (sf0[jp]     * sw[h] + sf1[jp]     * sw[128 + h]);
        float v1 = sd[jp + 1] * (sf0[jp + 1] * sw[h] + sf1[jp + 1] * sw[128 + h]);
        *(__half2*)(g_Xs + ((size_t)b * Hh + h) * Nn + j0 + jp) = __floats2half2_rn(v0, v1);
    }
}

// ---------------- WMMA GEMM: C(128 x 256tile) = A(128 x K) * B(K x Ntile) ----------------
// 8 warps (2x4), warp tile 64x64, BK=64, 3-stage cp.async pipeline.
#define BM 128
#define BN 256
#define BK 64
#define LDA_S 72
#define LDB_S 264
#define LDC_S 264
#define A_ST (BM * LDA_S)
#define B_ST (BK * LDB_S)
#define STAGE_H (A_ST + B_ST)
#define GEMM_SMEM (3 * STAGE_H * 2)   // 156672 B

// outMode: 0 = store C fp16; 1 = store C + pool atomics; 2 = scores only (no C store)
__global__ void __launch_bounds__(256) k_gemm(
    const __half* __restrict__ gA, size_t sA, int lda,
    const __half* __restrict__ gB, size_t sB, int ldb,
    __half* __restrict__ gC, size_t sC, int K,
    const float* __restrict__ cscale, const float* __restrict__ rbias,
    const float* __restrict__ brbias, int doRelu, int outMode,
    const float* __restrict__ pA3, const float* __restrict__ pab3,
    float* __restrict__ poolOut, float* __restrict__ scoresOut)
{
    extern __shared__ char smem[];
    __half* S = (__half*)smem;
    uint32_t sb32 = smem_u32(smem);
    int tid = threadIdx.x, warp = tid >> 5;
    int wm = warp >> 2, wn = warp & 3;
    int b = blockIdx.y, n0 = blockIdx.x * BN;
    const __half* A  = gA + (size_t)b * sA;
    const __half* Bp = gB + (size_t)b * sB;

    wmma::fragment<wmma::accumulator, 16, 16, 16, float> acc[4][4];
#pragma unroll
    for (int i = 0; i < 4; i++)
#pragma unroll
        for (int j = 0; j < 4; j++) wmma::fill_fragment(acc[i][j], 0.f);

    auto load_stage = [&](int st, int k0) {
        uint32_t as = sb32 + st * STAGE_H * 2;
        uint32_t bs = as + A_ST * 2;
#pragma unroll
        for (int t = 0; t < 4; t++) {
            int c = tid + t * 256;
            int ar = c >> 3, ak = (c & 7) << 3;
            cp16(as + (ar * LDA_S + ak) * 2, A + (size_t)ar * lda + k0 + ak);
        }
#pragma unroll
        for (int t = 0; t < 8; t++) {
            int c = tid + t * 256;
            int br = c >> 5, bn = (c & 31) << 3;
            cp16(bs + (br * LDB_S + bn) * 2, Bp + (size_t)(k0 + br) * ldb + n0 + bn);
        }
    };

    int KI = K >> 6;
    load_stage(0, 0); CP_COMMIT();
    load_stage(1, BK); CP_COMMIT();

    for (int i = 0; i < KI; i++) {
        if (i < KI - 1) CP_WAIT(1); else CP_WAIT(0);
        __syncthreads();
        if (i + 2 < KI) { load_stage((i + 2) % 3, (i + 2) * BK); CP_COMMIT(); }
        const __half* As = S + (i % 3) * STAGE_H;
        const __half* Bs = As + A_ST;
#pragma unroll
        for (int kk = 0; kk < BK; kk += 16) {
            wmma::fragment<wmma::matrix_a, 16, 16, 16, __half, wmma::row_major> af[4];
            wmma::fragment<wmma::matrix_b, 16, 16, 16, __half, wmma::row_major> bf[4];
#pragma unroll
            for (int x = 0; x < 4; x++)
                wmma::load_matrix_sync(af[x], As + (wm * 64 + x * 16) * LDA_S + kk, LDA_S);
#pragma unroll
            for (int y = 0; y < 4; y++)
                wmma::load_matrix_sync(bf[y], Bs + kk * LDB_S + wn * 64 + y * 16, LDB_S);
#pragma unroll
            for (int x = 0; x < 4; x++)
#pragma unroll
                for (int y = 0; y < 4; y++)
                    wmma::mma_sync(acc[x][y], af[x], bf[y], acc[x][y]);
        }
    }
    __syncthreads();

    float* Cs = (float*)smem;
#pragma unroll
    for (int x = 0; x < 4; x++)
#pragma unroll
        for (int y = 0; y < 4; y++)
            wmma::store_matrix_sync(Cs + (wm * 64 + x * 16) * LDC_S + wn * 64 + y * 16,
                                    acc[x][y], LDC_S, wmma::mem_row_major);
    __syncthreads();

    if (outMode == 2) {
        // scores: per-column reduction over m with relu(acc + ab2[m]) * A3[m]
        float* sA3 = (float*)(smem + BM * LDC_S * 4);
        float* sbv = sA3 + 128;
        if (tid < 128) { sA3[tid] = pA3[tid]; sbv[tid] = rbias[tid]; }
        __syncthreads();
        int n = tid;                       // 256 threads, 256 cols
        float accv = 0.f;
#pragma unroll 4
        for (int m = 0; m < 128; m++) {
            float v = Cs[m * LDC_S + n] + sbv[m];
            v = fmaxf(v, 0.f);
            accv += v * sA3[m];
        }
        scoresOut[(size_t)b * Nn + n0 + n] = 10.f * (accv + pab3[0]);
        return;
    }

    const float* cs = cscale ? cscale + (size_t)b * Nn + n0 : nullptr;
    const float* bbp = brbias ? brbias + b * Hh : nullptr;
#pragma unroll
    for (int t = 0; t < 16; t++) {
        int c = tid + t * 256;                   // 4096 chunks of 8 halves
        int m = c >> 5, nc = (c & 31) << 3;
        float rbv = 0.f;
        if (rbias) rbv += rbias[m];
        if (bbp)   rbv += bbp[m];
        __half2 hb[4];
#pragma unroll
        for (int e = 0; e < 8; e += 2) {
            float v0 = Cs[m * LDC_S + nc + e];
            float v1 = Cs[m * LDC_S + nc + e + 1];
            if (cs) { v0 *= cs[nc + e]; v1 *= cs[nc + e + 1]; }
            v0 += rbv; v1 += rbv;
            if (doRelu) { v0 = fmaxf(v0, 0.f); v1 = fmaxf(v1, 0.f); }
            hb[e >> 1] = __floats2half2_rn(v0, v1);
        }
        *(uint4*)(gC + (size_t)b * sC + (size_t)m * Nn + n0 + nc) = *(const uint4*)hb;
    }
    if (outMode == 1) {
        // pool partial sums: thread t -> row m = t&127, half = t>>7
        int m = tid & 127, hf = tid >> 7;
        float rbv = rbias ? rbias[m] : 0.f;
        float part = 0.f;
#pragma unroll 4
        for (int n = hf * 128; n < hf * 128 + 128; n++) {
            float v = Cs[m * LDC_S + n];
            if (cs) v *= cs[n];
            v += rbv;
            part += fmaxf(v, 0.f);
        }
        atomicAdd(&poolOut[b * Hh + m], part);
    }
}

// ---------------- bias1, final ----------------
__global__ void k_bias1(const float* __restrict__ A1, const float* __restrict__ ab1,
                        const float* __restrict__ ms) {
    int b = blockIdx.x, h = threadIdx.x;
    const float inv = 1.f / 2048.f;
    float acc = ab1[h];
    for (int k = 0; k < Hh; k++)
        acc += g_pool[b * Hh + k] * inv * A1[(Hh + k) * Hh + h] + ms[k] * A1[(2 * Hh + k) * Hh + h];
    g_bias1[b * Hh + h] = acc;
}

__global__ void k_final(const int* __restrict__ cand, const int* __restrict__ action,
                        const float* __restrict__ C1, const float* __restrict__ cb1,
                        const float* __restrict__ C2, const float* __restrict__ cb2,
                        float* __restrict__ out)
{
    int b = blockIdx.x, tid = threadIdx.x;
    __shared__ float sv[Nn];
    __shared__ float red[256];
    const float* sc = g_scores + b * Nn;
    const int* cd = cand + b * Nn;
    float mx = -3.4e38f;
    for (int i = tid; i < Nn; i += 256) mx = fmaxf(mx, sc[i]);
    red[tid] = mx; __syncthreads();
    for (int s = 128; s > 0; s >>= 1) { if (tid < s) red[tid] = fmaxf(red[tid], red[tid + s]); __syncthreads(); }
    float smax = red[0]; __syncthreads();
    float sum = 0.f;
    for (int i = tid; i < Nn; i += 256) { float e = expf(sc[i] - smax); sv[i] = e; sum += e; }
    red[tid] = sum; __syncthreads();
    for (int s = 128; s > 0; s >>= 1) { if (tid < s) red[tid] += red[tid + s]; __syncthreads(); }
    float tot = red[0]; __syncthreads();
    float m2 = -3.4e38f;
    for (int i = tid; i < Nn; i += 256) {
        float z = cd[i] ? (sv[i] / tot) : -1e9f;
        sv[i] = z; m2 = fmaxf(m2, z);
    }
    red[tid] = m2; __syncthreads();
    for (int s = 128; s > 0; s >>= 1) { if (tid < s) red[tid] = fmaxf(red[tid], red[tid + s]); __syncthreads(); }
    m2 = red[0]; __syncthreads();
    float se = 0.f;
    for (int i = tid; i < Nn; i += 256) se += expf(sv[i] - m2);
    red[tid] = se; __syncthreads();
    for (int s = 128; s > 0; s >>= 1) { if (tid < s) red[tid] += red[tid + s]; __syncthreads(); }
    float lse = logf(red[0]); __syncthreads();
    float ent = 0.f;
    for (int i = tid; i < Nn; i += 256) { float lp = sv[i] - m2 - lse; float p = expf(lp); ent -= p * lp; }
    red[tid] = ent; __syncthreads();
    for (int s = 128; s > 0; s >>= 1) { if (tid < s) red[tid] += red[tid + s]; __syncthreads(); }
    float entropy = red[0];
    if (tid == 0) {
        int a = action[b];
        out[b]      = (float)a;
        out[16 + b] = sv[a] - m2 - lse;
        out[32 + b] = entropy;
    }
    if (tid < 32) {
        const float inv = 1.f / 2048.f;
        float acc = cb1[tid];
        for (int h = 0; h < Hh; h++) acc += g_pool[b * Hh + h] * inv * C1[h * 32 + tid];
        float r = fmaxf(acc, 0.f) * C2[tid];
#pragma unroll
        for (int o = 16; o > 0; o >>= 1) r += __shfl_down_sync(0xffffffff, r, o);
        if (tid == 0) out[48 + b] = r + cb2[0];
    }
}

// ---------------- launch ----------------
extern "C" void kernel_launch(void* const* d_in, const int* in_sizes, int n_in,
                              void* d_out, int out_size) {
    const float* features = (const float*)d_in[0];
    const int*   adj      = (const int*)d_in[1];
    const int*   cand     = (const int*)d_in[2];
    const int*   action   = (const int*)d_in[3];
    const float* W1  = (const float*)d_in[4];
    const float* b1  = (const float*)d_in[5];
    const float* W2  = (const float*)d_in[6];
    const float* b2  = (const float*)d_in[7];
    const float* W3  = (const float*)d_in[8];
    const float* b3  = (const float*)d_in[9];
    const float* ms  = (const float*)d_in[10];
    const float* A1  = (const float*)d_in[11];
    const float* ab1 = (const float*)d_in[12];
    const float* A2  = (const float*)d_in[13];
    const float* ab2 = (const float*)d_in[14];
    const float* A3  = (const float*)d_in[15];
    const float* ab3 = (const float*)d_in[16];
    const float* C1  = (const float*)d_in[17];
    const float* cb1 = (const float*)d_in[18];
    const float* C2  = (const float*)d_in[19];
    const float* cb2 = (const float*)d_in[20];
    float* out = (float*)d_out;

    void *pAh, *pdeg, *pdis, *pXs, *ph, *pa1, *pw16, *pbias1, *ppool, *pscores;
    cudaGetSymbolAddress(&pAh,  g_Ah);
    cudaGetSymbolAddress(&pdeg, g_deg);
    cudaGetSymbolAddress(&pdis, g_dis);
    cudaGetSymbolAddress(&pXs,  g_Xs);
    cudaGetSymbolAddress(&ph,   g_h);
    cudaGetSymbolAddress(&pa1,  g_a1);
    cudaGetSymbolAddress(&pw16, g_w16);
    cudaGetSymbolAddress(&pbias1, g_bias1);
    cudaGetSymbolAddress(&ppool, g_pool);
    cudaGetSymbolAddress(&pscores, g_scores);

    __half* Ah   = (__half*)pAh;
    __half* Xs   = (__half*)pXs;
    __half* Hbuf = (__half*)ph;
    __half* A1b  = (__half*)pa1;
    __half* W16  = (__half*)pw16;
    float*  dis  = (float*)pdis;
    float*  bias1 = (float*)pbias1;
    float*  pool = (float*)ppool;
    float*  scores = (float*)pscores;

    const size_t HN = (size_t)Hh * Nn;
    const size_t NN = (size_t)Nn * Nn;

    cudaFuncSetAttribute(k_gemm, cudaFuncAttributeMaxDynamicSharedMemorySize, GEMM_SMEM);

    cudaMemsetAsync(pdeg, 0, Bb * Nn * sizeof(float));
    cudaMemsetAsync(ppool, 0, Bb * Hh * sizeof(float));
    k_deg_convert<<<dim3(32, Bb), 256>>>(adj);
    k_dis<<<(Bb * Nn) / 256, 256>>>();
    k_convw<<<(Hh * Hh) / 256, 256>>>(W2, W3, A1, A2);
    k_xs1<<<dim3(16, Bb), 256>>>(features, W1);

    dim3 gg(Nn / BN, Bb);
    // layer 1: h[h][i] = relu(dis_i * Σ_j Xs[h][j] Ah[j][i] + b1[h])
    k_gemm<<<gg, 256, GEMM_SMEM>>>(Xs, HN, Nn, Ah, NN, Nn, Hbuf, HN, Nn,
                                   dis, b1, nullptr, 1, 0, nullptr, nullptr, nullptr, nullptr);
    // layer 2 projection + aggregation
    k_gemm<<<gg, 256, GEMM_SMEM>>>(W16, 0, Hh, Hbuf, HN, Nn, Xs, HN, Hh,
                                   dis, nullptr, nullptr, 0, 0, nullptr, nullptr, nullptr, nullptr);
    k_gemm<<<gg, 256, GEMM_SMEM>>>(Xs, HN, Nn, Ah, NN, Nn, Hbuf, HN, Nn,
                                   dis, b2, nullptr, 1, 0, nullptr, nullptr, nullptr, nullptr);
    // layer 3 (pool fused into epilogue)
    k_gemm<<<gg, 256, GEMM_SMEM>>>(W16 + Hh * Hh, 0, Hh, Hbuf, HN, Nn, Xs, HN, Hh,
                                   dis, nullptr, nullptr, 0, 0, nullptr, nullptr, nullptr, nullptr);
    k_gemm<<<gg, 256, GEMM_SMEM>>>(Xs, HN, Nn, Ah, NN, Nn, Hbuf, HN, Nn,
                                   dis, b3, nullptr, 1, 1, nullptr, nullptr, pool, nullptr);
    // actor
    k_bias1<<<Bb, Hh>>>(A1, ab1, ms);
    k_gemm<<<gg, 256, GEMM_SMEM>>>(W16 + 2 * Hh * Hh, 0, Hh, Hbuf, HN, Nn, A1b, HN, Hh,
                                   nullptr, nullptr, bias1, 1, 0, nullptr, nullptr, nullptr, nullptr);
    // a2 GEMM with fused scores reduction (no C store)
    k_gemm<<<gg, 256, GEMM_SMEM>>>(W16 + 3 * Hh * Hh, 0, Hh, A1b, HN, Nn, A1b, HN, Hh,
                                   nullptr, ab2, nullptr, 1, 2, A3, ab3, nullptr, scores);
    k_final<<<Bb, 256>>>(cand, action, C1, cb1, C2, cb2, out);
}